// round 7
// baseline (speedup 1.0000x reference)
#include <cuda_runtime.h>

namespace {
constexpr int IMG_H = 512, IMG_W = 512, CH = 3, NB = 2;
constexpr int TW = 32, TH = 32, HALO = 3;       // 32x32 tile, 4 px per thread
constexpr int SMW = TW + 2 * HALO;   // 38
constexpr int SMH = TH + 2 * HALO;   // 38
constexpr float L2E = 1.4426950408889634f;          // log2(e)
constexpr float C50L2E = 72.13475204444817f;        // 50 * log2(e)
}

__device__ __forceinline__ float ex2f(float v) {
    float r;
    asm("ex2.approx.f32 %0, %1;" : "=f"(r) : "f"(v));
    return r;
}
__device__ __forceinline__ float rcpf(float v) {
    float r;
    asm("rcp.approx.f32 %0, %1;" : "=f"(r) : "f"(v));
    return r;
}
__device__ __forceinline__ int refl(int p, int n) {
    return p < 0 ? -p : (p >= n ? 2 * n - 2 - p : p);
}

__global__ __launch_bounds__(256, 4)
void afilt_kernel(const float* __restrict__ xin,
                  const float* __restrict__ gin,
                  const float* __restrict__ w0,
                  float* __restrict__ out)
{
    // Packed per-pixel tiles: one LDS.128 + one LDS.64 fetch everything for a tap.
    __shared__ float4 sA[SMH][SMW];   // {g0, g1, g2, x0}
    __shared__ float2 sB[SMH][SMW];   // {x1, x2}

    const int tx = threadIdx.x & 31;
    const int ty = threadIdx.x >> 5;            // 0..7, owns 4 vertical pixels
    const int bx = blockIdx.x * TW;
    const int by = blockIdx.y * TH;
    const int b  = blockIdx.z;

    const size_t hw = (size_t)IMG_H * IMG_W;

    // Cooperative reflect-padded tile fill (38x38 = 1444 px, 256 threads)
    for (int idx = threadIdx.x; idx < SMH * SMW; idx += 256) {
        const int r = idx / SMW;
        const int c = idx - r * SMW;
        const int gy = refl(by + r - HALO, IMG_H);
        const int gx = refl(bx + c - HALO, IMG_W);
        const size_t off = (size_t)b * CH * hw + (size_t)gy * IMG_W + gx;
        float4 a;
        a.x = gin[off];
        a.y = gin[off + hw];
        a.z = gin[off + 2 * hw];
        a.w = xin[off];
        float2 v;
        v.x = xin[off + hw];
        v.y = xin[off + 2 * hw];
        sA[r][c] = a;
        sB[r][c] = v;
    }

    const int px  = bx + tx;
    const int py0 = by + ty * 4;                // first of this thread's 4 pixels

    // Per-pixel half-kernel logits: 4 contiguous float4 rows per pixel.
    // Softmax Z and the max-shift both cancel in num/den; |w| stays small, so raw
    // logits go straight into exp2 — only 4 weight regs live per active pixel.
    const float4* w4 = reinterpret_cast<const float4*>(w0)
                     + ((size_t)b * hw + (size_t)py0 * IMG_W + px) * 4;

    __syncthreads();

    const int sy = ty * 4;
    float cx[4], cy[4], cz[4];
    #pragma unroll
    for (int p = 0; p < 4; p++) {
        const float4 c = sA[sy + HALO + p][tx + HALO];
        cx[p] = c.x; cy[p] = c.y; cz[p] = c.z;
    }

    float n0[4], n1[4], n2[4], dd[4];
    #pragma unroll
    for (int p = 0; p < 4; p++) { n0[p] = n1[p] = n2[p] = dd[p] = 0.f; }

    // 10 shared rows serve 4 vertical pixels: pixel p uses rows p..p+6.
    #pragma unroll
    for (int r = 0; r < 10; r++) {
        float4 wr[4];
        #pragma unroll
        for (int p = 0; p < 4; p++) {
            if (r >= p && r <= p + 6) {
                const int dr = r - p;
                const int mi = (dr < 4) ? dr : 6 - dr;   // reflect map of kernel row
                float4 t = w4[(size_t)p * IMG_W * 4 + mi];
                t.x *= L2E; t.y *= L2E; t.z *= L2E; t.w *= L2E;
                wr[p] = t;
            }
        }
        #pragma unroll
        for (int j = 0; j < 7; j++) {
            const float4 a  = sA[sy + r][tx + j];   // g0,g1,g2,x0
            const float2 vv = sB[sy + r][tx + j];   // x1,x2
            const int mj = (j < 4) ? j : 6 - j;     // reflect map of kernel col
            #pragma unroll
            for (int p = 0; p < 4; p++) {
                if (r >= p && r <= p + 6) {
                    const float s = fabsf(a.x - cx[p]) + fabsf(a.y - cy[p])
                                  + fabsf(a.z - cz[p]);
                    const float wt = (mj == 0) ? wr[p].x : (mj == 1) ? wr[p].y
                                   : (mj == 2) ? wr[p].z : wr[p].w;
                    const float e = ex2f(wt - C50L2E * (s * s));
                    n0[p] += a.w  * e;
                    n1[p] += vv.x * e;
                    n2[p] += vv.y * e;
                    dd[p] += e;
                }
            }
        }
    }

    const size_t ob = (size_t)b * CH * hw + (size_t)py0 * IMG_W + px;
    #pragma unroll
    for (int p = 0; p < 4; p++) {
        const float inv = rcpf(dd[p]);
        out[ob + (size_t)p * IMG_W]          = n0[p] * inv;
        out[ob + (size_t)p * IMG_W + hw]     = n1[p] * inv;
        out[ob + (size_t)p * IMG_W + 2 * hw] = n2[p] * inv;
    }
}

extern "C" void kernel_launch(void* const* d_in, const int* in_sizes, int n_in,
                              void* d_out, int out_size)
{
    const float* x  = (const float*)d_in[0];
    const float* g  = (const float*)d_in[1];
    const float* w0 = (const float*)d_in[2];
    float* out = (float*)d_out;

    dim3 grid(IMG_W / TW, IMG_H / TH, NB);   // 16 x 16 x 2
    dim3 block(256);
    afilt_kernel<<<grid, block>>>(x, g, w0, out);
}